// round 9
// baseline (speedup 1.0000x reference)
#include <cuda_runtime.h>

typedef unsigned long long u64;

#define H       128
#define SEQ     1024
#define MBLK    4
#define NCTAS   128
#define NTHR    256
#define COUT    10

#define NG      16          // 4-k groups per thread (64 k's, kh half)
#define RG      6           // register-resident weight groups (96 regs)
#define SG      (NG - RG)   // 10 groups from smem

#define HSTRIDE 136         // h row stride in floats (mod 32 = 8 -> bank spread)
#define HBUF    (MBLK * HSTRIDE)    // 544 floats

// h skew: float offset of h[k] within a row = k + (k>>6)*4
// kh=1 half starts at 68 -> +4 banks vs kh=0: the two 16B spans of a
// broadcast load are bank-disjoint -> 1 wavefront.
__device__ __forceinline__ int hoff(int k) { return k + ((k >> 6) << 2); }

// ---- dynamic smem layout (bytes, 16B aligned) ----
#define WS_OFF    0
#define WS_BYTES  (SG * 4 * NTHR * 16)      // 163840
#define XS_OFF    (WS_OFF + WS_BYTES)
#define XS_BYTES  (MBLK * SEQ * 4)          // 16384
#define WPS_OFF   (XS_OFF + XS_BYTES)
#define WPS_BYTES (H * COUT * 4)            // 5120
#define HB_OFF    (WPS_OFF + WPS_BYTES)
#define HB_BYTES  (2 * HBUF * 4)            // 4352
#define SMEM_TOTAL (HB_OFF + HB_BYTES + 64) // ~190 KB <= 227 KB

__device__ __forceinline__ u64 pk2(float lo, float hi) {
    u64 r;
    asm("mov.b64 %0, {%1, %2};" : "=l"(r) : "f"(lo), "f"(hi));
    return r;
}
__device__ __forceinline__ void upk2(u64 v, float& lo, float& hi) {
    asm("mov.b64 {%0, %1}, %2;" : "=f"(lo), "=f"(hi) : "l"(v));
}
__device__ __forceinline__ u64 ffma2(u64 a, u64 b, u64 c) {
    u64 d;
    asm("fma.rn.f32x2 %0, %1, %2, %3;" : "=l"(d) : "l"(a), "l"(b), "l"(c));
    return d;
}

// Fused LSTM cell epilogue: h = tanh(c')*sigmoid(zo), c' = tanh(zg)*sigmoid(zi) + c*sigmoid(zf)
// 5 exp + 3 rcp = 8 MUFU. Overflow-safe: exp->inf makes denominators inf -> quotient 0.
__device__ __forceinline__ float lstm_cell(float zg, float zi, float zf, float zo, float& c) {
    float eg = __expf(-2.0f * fabsf(zg));
    float ei = __expf(-zi);
    float ef = __expf(-zf);
    float eo = __expf(-zo);
    float gi = __fdividef(copysignf(1.0f - eg, zg), (1.0f + eg) * (1.0f + ei));
    float cf = __fdividef(c, 1.0f + ef);
    float cn = gi + cf;
    float ec = __expf(-2.0f * fabsf(cn));
    float h  = __fdividef(copysignf(1.0f - ec, cn), (1.0f + ec) * (1.0f + eo));
    c = cn;
    return h;
}

__global__ void __launch_bounds__(NTHR, 1)
lstm_persistent_kernel(const float* __restrict__ x,
                       const float* __restrict__ Wgx, const float* __restrict__ Wgh, const float* __restrict__ bg,
                       const float* __restrict__ Wix, const float* __restrict__ Wih, const float* __restrict__ bi,
                       const float* __restrict__ Wfx, const float* __restrict__ Wfh, const float* __restrict__ bf,
                       const float* __restrict__ Wox, const float* __restrict__ Woh, const float* __restrict__ bo,
                       const float* __restrict__ Wph, const float* __restrict__ bp,
                       float* __restrict__ out)
{
    extern __shared__ char smem[];
    ulonglong2* ws = (ulonglong2*)(smem + WS_OFF);
    float*     xsm = (float*)(smem + XS_OFF);
    float*     wps = (float*)(smem + WPS_OFF);
    float*      hb = (float*)(smem + HB_OFF);   // two skewed h buffers

    const int tid = threadIdx.x;
    const int kh  = tid & 1;        // k-half: [kh*64, kh*64+64); partner = adjacent lane
    const int n   = tid >> 1;       // gate column (owns cols n of all 4 gates)
    const int m0  = blockIdx.x * MBLK;
    const int mr  = kh * 2;         // this thread's gate-phase rows: mr, mr+1
    const int om  = 2 - mr;         // partner's rows

    // ---- smem weights: groups RG..NG-1 of slice (kh, n) ----
    // ws[(sg*4+q)*NTHR + tid]: q0={g,i}(k0,k1) q1={f,o}(k0,k1) q2={g,i}(k2,k3) q3={f,o}(k2,k3)
#pragma unroll
    for (int sg = 0; sg < SG; sg++) {
        int k0 = kh * 64 + (RG + sg) * 4;
        ulonglong2 v;
        v.x = pk2(Wgh[(k0+0)*H+n], Wgh[(k0+1)*H+n]);
        v.y = pk2(Wih[(k0+0)*H+n], Wih[(k0+1)*H+n]);
        ws[(sg*4+0)*NTHR + tid] = v;
        v.x = pk2(Wfh[(k0+0)*H+n], Wfh[(k0+1)*H+n]);
        v.y = pk2(Woh[(k0+0)*H+n], Woh[(k0+1)*H+n]);
        ws[(sg*4+1)*NTHR + tid] = v;
        v.x = pk2(Wgh[(k0+2)*H+n], Wgh[(k0+3)*H+n]);
        v.y = pk2(Wih[(k0+2)*H+n], Wih[(k0+3)*H+n]);
        ws[(sg*4+2)*NTHR + tid] = v;
        v.x = pk2(Wfh[(k0+2)*H+n], Wfh[(k0+3)*H+n]);
        v.y = pk2(Woh[(k0+2)*H+n], Woh[(k0+3)*H+n]);
        ws[(sg*4+3)*NTHR + tid] = v;
    }

    // ---- register weights: groups 0..RG-1 (8 u64 each = 96 regs) ----
    u64 wreg[RG][8];
#pragma unroll
    for (int g = 0; g < RG; g++) {
        int k0 = kh * 64 + g * 4;
        wreg[g][0] = pk2(Wgh[(k0+0)*H+n], Wgh[(k0+1)*H+n]);
        wreg[g][1] = pk2(Wih[(k0+0)*H+n], Wih[(k0+1)*H+n]);
        wreg[g][2] = pk2(Wfh[(k0+0)*H+n], Wfh[(k0+1)*H+n]);
        wreg[g][3] = pk2(Woh[(k0+0)*H+n], Woh[(k0+1)*H+n]);
        wreg[g][4] = pk2(Wgh[(k0+2)*H+n], Wgh[(k0+3)*H+n]);
        wreg[g][5] = pk2(Wih[(k0+2)*H+n], Wih[(k0+3)*H+n]);
        wreg[g][6] = pk2(Wfh[(k0+2)*H+n], Wfh[(k0+3)*H+n]);
        wreg[g][7] = pk2(Woh[(k0+2)*H+n], Woh[(k0+3)*H+n]);
    }

    // ---- gate-phase params: thread owns cells (mr, n), (mr+1, n) ----
    const float wxg = Wgx[n], wxi = Wix[n], wxf = Wfx[n], wxo = Wox[n];
    float bG[2], bI[2], bF[2], bO[2];
#pragma unroll
    for (int j = 0; j < 2; j++) {
        bG[j] = bg[(m0+mr+j)*H+n];
        bI[j] = bi[(m0+mr+j)*H+n];
        bF[j] = bf[(m0+mr+j)*H+n];
        bO[j] = bo[(m0+mr+j)*H+n];
    }

    // ---- preload x, Wph, zero both h buffers ----
    for (int i = tid; i < MBLK * SEQ; i += NTHR) {
        int mm = i >> 10, tt = i & (SEQ - 1);
        xsm[i] = x[(m0+mm)*SEQ + tt];
    }
    for (int i = tid; i < H * COUT; i += NTHR) wps[i] = Wph[i];
    for (int i = tid; i < 2 * HBUF; i += NTHR) hb[i] = 0.0f;
    float c0 = 0.0f, c1 = 0.0f;
    __syncthreads();

    // per-thread constant offsets
    const int hload0 = kh * 68;                         // skewed base of this kh half
    const int hst0 = (mr + 0) * HSTRIDE + hoff(n);      // own h store offsets
    const int hst1 = (mr + 1) * HSTRIDE + hoff(n);
    const float* x0 = xsm + (mr + 0) * SEQ;
    const float* x1 = xsm + (mr + 1) * SEQ;

    // ---- time loop: ONE barrier per step ----
    for (int t = 0; t < SEQ; t++) {
        const float* hr = hb + ((t & 1) ? HBUF : 0);
        float*       hw = hb + ((t & 1) ? 0 : HBUF);

        u64 acc[4][4];   // [gate][m], k-pair packed (even/odd k in lo/hi)
#pragma unroll
        for (int gg = 0; gg < 4; gg++)
#pragma unroll
            for (int m = 0; m < 4; m++) acc[gg][m] = 0ull;

#pragma unroll
        for (int g = 0; g < NG; g++) {
            u64 wg0, wi0, wf0, wo0, wg1, wi1, wf1, wo1;
            if (g < RG) {
                wg0 = wreg[g][0]; wi0 = wreg[g][1]; wf0 = wreg[g][2]; wo0 = wreg[g][3];
                wg1 = wreg[g][4]; wi1 = wreg[g][5]; wf1 = wreg[g][6]; wo1 = wreg[g][7];
            } else {
                int sg = g - RG;
                ulonglong2 q0 = ws[(sg*4+0)*NTHR + tid];
                ulonglong2 q1 = ws[(sg*4+1)*NTHR + tid];
                ulonglong2 q2 = ws[(sg*4+2)*NTHR + tid];
                ulonglong2 q3 = ws[(sg*4+3)*NTHR + tid];
                wg0 = q0.x; wi0 = q0.y; wf0 = q1.x; wo0 = q1.y;
                wg1 = q2.x; wi1 = q2.y; wf1 = q3.x; wo1 = q3.y;
            }
            const int hbase = hload0 + (g << 2);
#pragma unroll
            for (int m = 0; m < 4; m++) {
                // broadcast 16B: {h[k0..k3]} of row m; 2 kh spans bank-disjoint -> 1 wf
                ulonglong2 hu = *(const ulonglong2*)(hr + m * HSTRIDE + hbase);
                acc[0][m] = ffma2(hu.x, wg0, acc[0][m]);
                acc[1][m] = ffma2(hu.x, wi0, acc[1][m]);
                acc[2][m] = ffma2(hu.x, wf0, acc[2][m]);
                acc[3][m] = ffma2(hu.x, wo0, acc[3][m]);
                acc[0][m] = ffma2(hu.y, wg1, acc[0][m]);
                acc[1][m] = ffma2(hu.y, wi1, acc[1][m]);
                acc[2][m] = ffma2(hu.y, wf1, acc[2][m]);
                acc[3][m] = ffma2(hu.y, wo1, acc[3][m]);
            }
        }

        // collapse k-pairs -> p[gate][m] (this thread's kh-partial sums)
        float p[4][4];
#pragma unroll
        for (int gg = 0; gg < 4; gg++)
#pragma unroll
            for (int m = 0; m < 4; m++) {
                float lo, hi;
                upk2(acc[gg][m], lo, hi);
                p[gg][m] = lo + hi;
            }

        // exchange kh-partials with adjacent lane: send partner's rows, get mine
        float rec[4][2];
#pragma unroll
        for (int gg = 0; gg < 4; gg++)
#pragma unroll
            for (int j = 0; j < 2; j++)
                rec[gg][j] = __shfl_xor_sync(0xFFFFFFFFu, p[gg][om + j], 1);

        // gates for the 2 owned cells
        {
            float xv = x0[t];
            float zg = p[0][mr]   + rec[0][0] + fmaf(xv, wxg, bG[0]);
            float zi = p[1][mr]   + rec[1][0] + fmaf(xv, wxi, bI[0]);
            float zf = p[2][mr]   + rec[2][0] + fmaf(xv, wxf, bF[0]);
            float zo = p[3][mr]   + rec[3][0] + fmaf(xv, wxo, bO[0]);
            hw[hst0] = lstm_cell(zg, zi, zf, zo, c0);
        }
        {
            float xv = x1[t];
            float zg = p[0][mr+1] + rec[0][1] + fmaf(xv, wxg, bG[1]);
            float zi = p[1][mr+1] + rec[1][1] + fmaf(xv, wxi, bI[1]);
            float zf = p[2][mr+1] + rec[2][1] + fmaf(xv, wxf, bF[1]);
            float zo = p[3][mr+1] + rec[3][1] + fmaf(xv, wxo, bO[1]);
            hw[hst1] = lstm_cell(zg, zi, zf, zo, c1);
        }

        __syncthreads();   // new h visible; double-buffer makes one barrier sufficient
    }

    // ---- final projection: h ends in buffer 0 after SEQ (even) steps ----
    const float* hf = hb;
    if (tid < MBLK * COUT) {
        int m = tid / COUT, cc = tid - m * COUT;
        float ssum = bp[(m0+m)*COUT + cc];
#pragma unroll 16
        for (int k = 0; k < H; k++)
            ssum = fmaf(hf[m * HSTRIDE + hoff(k)], wps[k*COUT + cc], ssum);
        out[(m0+m)*COUT + cc] = ssum;
    }
}

extern "C" void kernel_launch(void* const* d_in, const int* in_sizes, int n_in,
                              void* d_out, int out_size) {
    const float* x   = (const float*)d_in[0];
    const float* Wgx = (const float*)d_in[1];
    const float* Wgh = (const float*)d_in[2];
    const float* bg  = (const float*)d_in[3];
    const float* Wix = (const float*)d_in[4];
    const float* Wih = (const float*)d_in[5];
    const float* bi  = (const float*)d_in[6];
    const float* Wfx = (const float*)d_in[7];
    const float* Wfh = (const float*)d_in[8];
    const float* bf  = (const float*)d_in[9];
    const float* Wox = (const float*)d_in[10];
    const float* Woh = (const float*)d_in[11];
    const float* bo  = (const float*)d_in[12];
    const float* Wph = (const float*)d_in[13];
    const float* bp  = (const float*)d_in[14];
    float* out = (float*)d_out;

    cudaFuncSetAttribute(lstm_persistent_kernel,
                         cudaFuncAttributeMaxDynamicSharedMemorySize, SMEM_TOTAL);

    lstm_persistent_kernel<<<NCTAS, NTHR, SMEM_TOTAL>>>(
        x, Wgx, Wgh, bg, Wix, Wih, bi, Wfx, Wfh, bf, Wox, Woh, bo, Wph, bp, out);
}